// round 3
// baseline (speedup 1.0000x reference)
#include <cuda_runtime.h>

#define THREADS 256

// ---- problem constants ----
#define Cc    4
#define Tt    1000
#define FQn   1025
#define Dd    384
#define INF   128      // W*C
#define Mrows 8000     // B*T
#define KB    45

// ---- tiling ----
#define MT    128      // rows per CTA tile
#define DC    64       // D chunk
#define NCH   (Dd / DC)
#define XP    (MT + 4) // Xs row stride (K-major), pad for banks
#define WPD   (DC + 4) // Wpre row stride
#define HP    (MT + 4) // Hs row stride (d-major)
#define SMEM_FLOATS (128 * XP + 128 * WPD + DC * HP + DC * INF)

// Band tables (disjoint frequency groups: widths 4..32 then 32s, last 23)
__constant__ int c_start[KB] = {
    0,4,9,15,22,30,39,49,60,72,85,99,114,130,147,165,184,204,225,247,
    270,294,319,345,372,400,429,459,490,522,554,586,618,650,682,714,
    746,778,810,842,874,906,938,970,1002};
__constant__ int c_width[KB] = {
    4,5,6,7,8,9,10,11,12,13,14,15,16,17,18,19,20,21,22,23,
    24,25,26,27,28,29,30,31,32,32,32,32,32,32,32,32,
    32,32,32,32,32,32,32,32,23};

__global__ __launch_bounds__(THREADS, 1)
void bandsplit_fused(const float* __restrict__ x,
                     const float* __restrict__ w_pre,
                     const float* __restrict__ b_pre,
                     const float* __restrict__ w_post,
                     const float* __restrict__ b_post,
                     float* __restrict__ out)
{
    extern __shared__ float smem[];
    float* Xs  = smem;                 // [128][XP]   feature-major: Xs[kk][m]
    float* Wps = Xs + 128 * XP;        // [128][WPD]  Wpre chunk:   [kk][d]
    float* Hs  = Wps + 128 * WPD;      // [DC][HP]    h chunk:      [d][m]
    float* Wqs = Hs + DC * HP;         // [DC][INF]   Wpost chunk:  [d][o]

    const int k     = blockIdx.y;
    const int tile0 = blockIdx.x * MT;
    const int tid   = threadIdx.x;
    const int fs    = c_start[k];
    const int fw    = c_width[k];

    // ---- gather X tile: Xs[kk][m] = x[b, c, t, fs+w], kk = w*4 + c ----
    for (int i = tid; i < MT * 128; i += THREADS) {
        const int kk = i & 127;
        const int m  = i >> 7;
        const int w  = kk >> 2;
        const int c  = kk & 3;
        const int mg = tile0 + m;
        float v = 0.0f;
        if (w < fw && mg < Mrows) {
            const int b = mg / Tt;
            const int t = mg - b * Tt;
            v = x[((size_t)(b * Cc + c) * Tt + t) * FQn + fs + w];
        }
        Xs[kk * XP + m] = v;
    }

    // Y accumulators: 8 rows x 8 out-cols per thread (64x128 block tile... x2 row groups)
    float yacc[8][8];
    #pragma unroll
    for (int i = 0; i < 8; ++i)
        #pragma unroll
        for (int j = 0; j < 8; ++j) yacc[i][j] = 0.0f;

    const int m0 = (tid >> 4) * 8;   // row block (shared by both gemms)
    const int d0 = (tid & 15) * 4;   // gemm1 d-cols within chunk
    const int o0 = (tid & 15) * 8;   // gemm2 out-cols

    for (int ch = 0; ch < NCH; ++ch) {
        const int dbase = ch * DC;
        __syncthreads();   // previous chunk's GEMM2 reads complete

        // load w_pre chunk [128 x DC] into Wps[kk][d]
        for (int i = tid; i < 128 * (DC / 4); i += THREADS) {
            const int r  = i >> 4;            // DC/4 = 16 float4 per row
            const int c4 = (i & 15) << 2;
            const float4 v = *(const float4*)&w_pre[((size_t)k * INF + r) * Dd + dbase + c4];
            *(float4*)&Wps[r * WPD + c4] = v;
        }
        // load w_post chunk [DC x 128] into Wqs[d][o]
        for (int i = tid; i < DC * (INF / 4); i += THREADS) {
            const int r  = i >> 5;            // 128/4 = 32 float4 per row
            const int c4 = (i & 31) << 2;
            const float4 v = *(const float4*)&w_post[((size_t)k * Dd + dbase + r) * INF + c4];
            *(float4*)&Wqs[r * INF + c4] = v;
        }
        __syncthreads();

        // ---- GEMM1: h[m0..m0+7][d0..d0+3] over K=128 ----
        float h[8][4];
        #pragma unroll
        for (int i = 0; i < 8; ++i)
            #pragma unroll
            for (int j = 0; j < 4; ++j) h[i][j] = 0.0f;

        #pragma unroll 4
        for (int kk = 0; kk < 128; ++kk) {
            const float4 xa = *(const float4*)&Xs[kk * XP + m0];
            const float4 xb = *(const float4*)&Xs[kk * XP + m0 + 4];
            const float4 wv = *(const float4*)&Wps[kk * WPD + d0];
            const float xr[8] = {xa.x, xa.y, xa.z, xa.w, xb.x, xb.y, xb.z, xb.w};
            const float wr[4] = {wv.x, wv.y, wv.z, wv.w};
            #pragma unroll
            for (int i = 0; i < 8; ++i)
                #pragma unroll
                for (int j = 0; j < 4; ++j)
                    h[i][j] = fmaf(xr[i], wr[j], h[i][j]);
        }

        // add b_pre, store Hs[d][m] (d-major for GEMM2 vector loads)
        #pragma unroll
        for (int j = 0; j < 4; ++j) {
            const float bp = b_pre[k * Dd + dbase + d0 + j];
            float4 a, b2;
            a.x  = h[0][j] + bp; a.y  = h[1][j] + bp; a.z  = h[2][j] + bp; a.w  = h[3][j] + bp;
            b2.x = h[4][j] + bp; b2.y = h[5][j] + bp; b2.z = h[6][j] + bp; b2.w = h[7][j] + bp;
            *(float4*)&Hs[(d0 + j) * HP + m0]     = a;
            *(float4*)&Hs[(d0 + j) * HP + m0 + 4] = b2;
        }
        __syncthreads();

        // ---- GEMM2: yacc[8][8] += Hs[d][m] * Wqs[d][o] over DC ----
        #pragma unroll 2
        for (int dd = 0; dd < DC; ++dd) {
            const float4 ha = *(const float4*)&Hs[dd * HP + m0];
            const float4 hb = *(const float4*)&Hs[dd * HP + m0 + 4];
            const float4 wa = *(const float4*)&Wqs[dd * INF + o0];
            const float4 wb = *(const float4*)&Wqs[dd * INF + o0 + 4];
            const float hr[8] = {ha.x, ha.y, ha.z, ha.w, hb.x, hb.y, hb.z, hb.w};
            const float wr[8] = {wa.x, wa.y, wa.z, wa.w, wb.x, wb.y, wb.z, wb.w};
            #pragma unroll
            for (int i = 0; i < 8; ++i)
                #pragma unroll
                for (int j = 0; j < 8; ++j)
                    yacc[i][j] = fmaf(hr[i], wr[j], yacc[i][j]);
        }
    }

    // ---- epilogue: scatter (each (b,c,t,f) written exactly once globally) ----
    float bpost[8];
    #pragma unroll
    for (int j = 0; j < 8; ++j) bpost[j] = b_post[k * INF + o0 + j];

    #pragma unroll
    for (int i = 0; i < 8; ++i) {
        const int mg = tile0 + m0 + i;
        if (mg < Mrows) {
            const int b = mg / Tt;
            const int t = mg - b * Tt;
            #pragma unroll
            for (int j = 0; j < 8; ++j) {
                const int o = o0 + j;
                const int w = o >> 2;
                const int c = o & 3;
                if (w < fw) {
                    out[((size_t)(b * Cc + c) * Tt + t) * FQn + fs + w] = yacc[i][j] + bpost[j];
                }
            }
        }
    }
}

extern "C" void kernel_launch(void* const* d_in, const int* in_sizes, int n_in,
                              void* d_out, int out_size)
{
    (void)in_sizes; (void)n_in; (void)out_size;
    const float* x      = (const float*)d_in[0];
    const float* w_pre  = (const float*)d_in[1];
    const float* b_pre  = (const float*)d_in[2];
    const float* w_post = (const float*)d_in[3];
    const float* b_post = (const float*)d_in[4];
    float* out = (float*)d_out;

    const size_t smem_bytes = (size_t)SMEM_FLOATS * sizeof(float);  // ~165 KB
    cudaFuncSetAttribute(bandsplit_fused,
                         cudaFuncAttributeMaxDynamicSharedMemorySize,
                         (int)smem_bytes);

    dim3 grid((Mrows + MT - 1) / MT, KB);  // (63, 45)
    bandsplit_fused<<<grid, THREADS, smem_bytes>>>(x, w_pre, b_pre, w_post, b_post, out);
}

// round 5
// speedup vs baseline: 1.7870x; 1.7870x over previous
#include <cuda_runtime.h>
#include <cstdint>

#define THREADS 256

// ---- problem constants ----
#define Cc    4
#define Tt    1000
#define FQn   1025
#define Dd    384
#define INF   128      // W*C
#define Mrows 8000     // B*T
#define KB    45

// ---- tiling ----
#define MT    256      // rows per CTA (8 warps x 32 rows)
#define DC    32       // D chunk
#define NCH   (Dd / DC)   // 12

// ---- smem layout (uint32 units), everything stored in MMA fragment order ----
// X A-fragments : 16 m-tiles x 16 k-tiles x 128        = 32768
// Wpre B-frags  : 16 k-tiles x 2 n-pairs x 128         = 4096
// Wpost B-frags : 4 k-tiles  x 8 n-pairs x 128         = 4096
// H A-fragments : 16 m-tiles x 4 k-tiles x 128         = 8192
#define OFF_X   0
#define SZ_X    (16*16*128)
#define OFF_WP  (OFF_X + SZ_X)
#define SZ_WP   (16*2*128)
#define OFF_WQ  (OFF_WP + SZ_WP)
#define SZ_WQ   (4*8*128)
#define OFF_H   (OFF_WQ + SZ_WQ)
#define SZ_H    (16*4*128)
#define SMEM_U32 (OFF_H + SZ_H)      // 49152 u32 = 192 KB

// Band tables (disjoint frequency groups)
__constant__ int c_start[KB] = {
    0,4,9,15,22,30,39,49,60,72,85,99,114,130,147,165,184,204,225,247,
    270,294,319,345,372,400,429,459,490,522,554,586,618,650,682,714,
    746,778,810,842,874,906,938,970,1002};
__constant__ int c_width[KB] = {
    4,5,6,7,8,9,10,11,12,13,14,15,16,17,18,19,20,21,22,23,
    24,25,26,27,28,29,30,31,32,32,32,32,32,32,32,32,
    32,32,32,32,32,32,32,32,23};

__device__ __forceinline__ uint32_t f2tf(float f) {
    uint32_t r;
    asm("cvt.rna.tf32.f32 %0, %1;" : "=r"(r) : "f"(f));
    return r;
}

__device__ __forceinline__ void mma8(float* c, const uint4 a, uint32_t b0, uint32_t b1) {
    asm volatile(
        "mma.sync.aligned.m16n8k8.row.col.f32.tf32.tf32.f32 "
        "{%0,%1,%2,%3},{%4,%5,%6,%7},{%8,%9},{%0,%1,%2,%3};"
        : "+f"(c[0]), "+f"(c[1]), "+f"(c[2]), "+f"(c[3])
        : "r"(a.x), "r"(a.y), "r"(a.z), "r"(a.w), "r"(b0), "r"(b1));
}

__global__ __launch_bounds__(THREADS, 1)
void bandsplit_mma(const float* __restrict__ x,
                   const float* __restrict__ w_pre,
                   const float* __restrict__ b_pre,
                   const float* __restrict__ w_post,
                   const float* __restrict__ b_post,
                   float* __restrict__ out)
{
    extern __shared__ uint32_t sm[];
    __shared__ float bpre_sh[DC];
    __shared__ float bpost_sh[INF];

    const int k     = blockIdx.y;
    const int tile0 = blockIdx.x * MT;
    const int tid   = threadIdx.x;
    const int warp  = tid >> 5;
    const int lane  = tid & 31;
    const int fs    = c_start[k];
    const int fw    = c_width[k];

    for (int i = tid; i < INF; i += THREADS) bpost_sh[i] = b_post[k * INF + i];

    // ---- gather X into A-fragment layout (tf32) ----
    // one warp per (m, channel): lanes read 32 consecutive freqs (coalesced 128B)
    for (int task = warp; task < MT * Cc; task += 8) {
        const int m  = task >> 2;
        const int c  = task & 3;
        const int mg = tile0 + m;
        const int w  = lane;
        float v = 0.0f;
        if (mg < Mrows && w < fw) {
            const int b = mg / Tt;
            const int t = mg - b * Tt;
            v = x[((size_t)(b * Cc + c) * Tt + t) * FQn + fs + w];
        }
        // kk = w*4 + c ; A-frag: kt = kk>>3, lane_s = ((m&7)<<2)|c, reg = ((w&1)<<1)|((m>>3)&1)
        const int kt     = w >> 1;
        const int gm     = m >> 4;
        const int lane_s = ((m & 7) << 2) | c;
        const int reg    = ((w & 1) << 1) | ((m >> 3) & 1);
        sm[OFF_X + (((gm * 16 + kt) * 32 + lane_s) << 2) + reg] = f2tf(v);
    }

    // GEMM2 accumulators: 2 m-tiles x 16 n-tiles x 4 regs
    float yacc[2][16][4];
    #pragma unroll
    for (int mt = 0; mt < 2; ++mt)
        #pragma unroll
        for (int nt = 0; nt < 16; ++nt)
            #pragma unroll
            for (int e = 0; e < 4; ++e) yacc[mt][nt][e] = 0.0f;

    for (int ch = 0; ch < NCH; ++ch) {
        const int dbase = ch * DC;
        __syncthreads();   // previous chunk's MMA reads of WP/WQ/H complete

        // ---- stage w_pre chunk [128 x DC] as B-fragments ----
        for (int i = tid; i < 128 * DC; i += THREADS) {
            const int kk = i >> 5;
            const int d  = i & 31;
            const float v = w_pre[((size_t)k * INF + kk) * Dd + dbase + d];
            const int kt = kk >> 3, kr = kk & 7, nt = d >> 3, nc = d & 7;
            const int np = nt >> 1, p = nt & 1;
            const int lane_s = (nc << 2) | (kr & 3);
            const int reg    = (p << 1) | (kr >> 2);
            sm[OFF_WP + (((kt * 2 + np) * 32 + lane_s) << 2) + reg] = f2tf(v);
        }
        // ---- stage w_post chunk [DC x 128] as B-fragments ----
        for (int i = tid; i < DC * INF; i += THREADS) {
            const int d = i >> 7;
            const int o = i & 127;
            const float v = w_post[((size_t)k * Dd + dbase + d) * INF + o];
            const int kt = d >> 3, kr = d & 7, nt = o >> 3, nc = o & 7;
            const int np = nt >> 1, p = nt & 1;
            const int lane_s = (nc << 2) | (kr & 3);
            const int reg    = (p << 1) | (kr >> 2);
            sm[OFF_WQ + (((kt * 8 + np) * 32 + lane_s) << 2) + reg] = f2tf(v);
        }
        if (tid < DC) bpre_sh[tid] = b_pre[k * Dd + dbase + tid];
        __syncthreads();

        // ---- GEMM1: H[32 x DC] per warp, K = 128 ----
        float h[2][4][4];
        #pragma unroll
        for (int mt = 0; mt < 2; ++mt)
            #pragma unroll
            for (int nt = 0; nt < 4; ++nt)
                #pragma unroll
                for (int e = 0; e < 4; ++e) h[mt][nt][e] = 0.0f;

        {
            const uint4* XF  = (const uint4*)(sm + OFF_X);
            const uint4* WpF = (const uint4*)(sm + OFF_WP);
            #pragma unroll
            for (int kt = 0; kt < 16; ++kt) {
                const uint4 a0 = XF[((warp * 2 + 0) * 16 + kt) * 32 + lane];
                const uint4 a1 = XF[((warp * 2 + 1) * 16 + kt) * 32 + lane];
                #pragma unroll
                for (int np = 0; np < 2; ++np) {
                    const uint4 b = WpF[(kt * 2 + np) * 32 + lane];
                    mma8(h[0][np * 2],     a0, b.x, b.y);
                    mma8(h[1][np * 2],     a1, b.x, b.y);
                    mma8(h[0][np * 2 + 1], a0, b.z, b.w);
                    mma8(h[1][np * 2 + 1], a1, b.z, b.w);
                }
            }
        }

        // ---- repack H (+b_pre, tf32) into GEMM2 A-fragment layout (warp-private) ----
        #pragma unroll
        for (int e = 0; e < 4; ++e) {
            const int lane2 = (lane & 0x1C) | ((lane & 1) << 1) | (e & 1);
            const int reg2  = (((lane >> 1) & 1) << 1) | (e >> 1);
            const int col   = ((lane & 3) << 1) | (e & 1);
            #pragma unroll
            for (int mt = 0; mt < 2; ++mt)
                #pragma unroll
                for (int nt = 0; nt < 4; ++nt) {   // nt == k-tile of GEMM2
                    const int d = nt * 8 + col;
                    const float v = h[mt][nt][e] + bpre_sh[d];
                    sm[OFF_H + ((((warp * 2 + mt) * 4 + nt) * 32 + lane2) << 2) + reg2] = f2tf(v);
                }
        }
        __syncwarp();

        // ---- GEMM2: Y[32 x 128] += H[32 x DC] * Wpost[DC x 128] ----
        {
            const uint4* HF  = (const uint4*)(sm + OFF_H);
            const uint4* WqF = (const uint4*)(sm + OFF_WQ);
            #pragma unroll
            for (int kt = 0; kt < 4; ++kt) {
                const uint4 a0 = HF[((warp * 2 + 0) * 4 + kt) * 32 + lane];
                const uint4 a1 = HF[((warp * 2 + 1) * 4 + kt) * 32 + lane];
                #pragma unroll
                for (int np = 0; np < 8; ++np) {
                    const uint4 b = WqF[(kt * 8 + np) * 32 + lane];
                    mma8(yacc[0][np * 2],     a0, b.x, b.y);
                    mma8(yacc[1][np * 2],     a1, b.x, b.y);
                    mma8(yacc[0][np * 2 + 1], a0, b.z, b.w);
                    mma8(yacc[1][np * 2 + 1], a1, b.z, b.w);
                }
            }
        }
    }

    // ---- epilogue: stage Y in smem (reuse X/WP region), then coalesced scatter ----
    __syncthreads();
    float* Ybuf = (float*)sm;   // [m][c][w] : m stride 132, c stride 33
    #pragma unroll
    for (int e = 0; e < 4; ++e) {
        const int r   = (lane >> 2) + ((e >> 1) << 3);
        const int col = ((lane & 3) << 1) | (e & 1);
        #pragma unroll
        for (int mt = 0; mt < 2; ++mt) {
            const int m = warp * 32 + mt * 16 + r;
            #pragma unroll
            for (int nt = 0; nt < 16; ++nt) {
                const int o = nt * 8 + col;
                Ybuf[m * 132 + (o & 3) * 33 + (o >> 2)] = yacc[mt][nt][e] + bpost_sh[o];
            }
        }
    }
    __syncthreads();

    for (int task = warp; task < MT * Cc; task += 8) {
        const int m  = task >> 2;
        const int c  = task & 3;
        const int mg = tile0 + m;
        const int w  = lane;
        if (mg < Mrows && w < fw) {
            const int b = mg / Tt;
            const int t = mg - b * Tt;
            out[((size_t)(b * Cc + c) * Tt + t) * FQn + fs + w] = Ybuf[m * 132 + c * 33 + w];
        }
    }
}

extern "C" void kernel_launch(void* const* d_in, const int* in_sizes, int n_in,
                              void* d_out, int out_size)
{
    (void)in_sizes; (void)n_in; (void)out_size;
    const float* x      = (const float*)d_in[0];
    const float* w_pre  = (const float*)d_in[1];
    const float* b_pre  = (const float*)d_in[2];
    const float* w_post = (const float*)d_in[3];
    const float* b_post = (const float*)d_in[4];
    float* out = (float*)d_out;

    const size_t smem_bytes = (size_t)SMEM_U32 * sizeof(uint32_t);  // 192 KB
    cudaFuncSetAttribute(bandsplit_mma,
                         cudaFuncAttributeMaxDynamicSharedMemorySize,
                         (int)smem_bytes);

    dim3 grid((Mrows + MT - 1) / MT, KB);   // (32, 45)
    bandsplit_mma<<<grid, THREADS, smem_bytes>>>(x, w_pre, b_pre, w_post, b_post, out);
}